// round 14
// baseline (speedup 1.0000x reference)
#include <cuda_runtime.h>

#define D 8
#define H 256
#define MAXN 100352
#define MASKW (H/32)

// ---------------- scratch (device globals; zero-initialized at module load).
// Invariant: accumulator arrays are zero on entry to kernel_launch and are
// re-zeroed by the kernel that consumes them (graph-replay safe).
__device__ float d_mdiag[MAXN*D];  // mass diag pre-scaled by sqrt(0.5*g)
__device__ float d_qs[MAXN*D];     // q * norm_src
__device__ float d_nsrc[MAXN];
__device__ float d_ndst[MAXN];
__device__ int   d_degout[MAXN];   // accumulator (zeroed by k_prep)
__device__ int   d_degin[MAXN];    // accumulator (zeroed by k_prep)
__device__ float d_agg1[MAXN*D];   // accumulator (zeroed by k_mlp_fwd)
__device__ float d_ts[MAXN*D];
__device__ float d_agg2[MAXN*D];   // accumulator (zeroed by k_h)
__device__ float d_h[MAXN*D];
__device__ float d_gH[MAXN*D];     // accumulator (zeroed by k_final)
__device__ float d_gz1d[MAXN*D];
__device__ float d_tmp1[MAXN*D];   // accumulator (zeroed by k_mlp_bwd)
__device__ float d_tmp2[MAXN*D];   // accumulator (zeroed by k_final)
__device__ unsigned d_mask[MAXN*MASKW];

// ---------------- helpers ---------------------------------------------------
__device__ __forceinline__ void red_add_v4(float* p, float4 v) {
    asm volatile("red.global.add.v4.f32 [%0], {%1,%2,%3,%4};"
                 :: "l"(p), "f"(v.x), "f"(v.y), "f"(v.z), "f"(v.w) : "memory");
}

// ---------------- kernels ---------------------------------------------------
__global__ void k_deg(const int* __restrict__ src, const int* __restrict__ dst, int e) {
    int i = blockIdx.x * blockDim.x + threadIdx.x;
    if (i >= e) return;
    atomicAdd(&d_degout[src[i]], 1);
    atomicAdd(&d_degin[dst[i]], 1);
}

// norms, mass diag (pre-scaled by sqrt(0.5*g)), qs pre-scale, dHdP; zero deg
__global__ void k_prep(const float* __restrict__ q, const float* __restrict__ p,
                       const float* __restrict__ M, const float* __restrict__ grav,
                       float* __restrict__ out, int n) {
    int i = blockIdx.x * blockDim.x + threadIdx.x;
    if (i >= n) return;
    int dout = d_degout[i], din = d_degin[i];
    d_degout[i] = 0; d_degin[i] = 0;                      // restore invariant
    float ns = (dout > 0) ? rsqrtf((float)dout) : 1.0f;
    float nd = (din  > 0) ? rsqrtf((float)din)  : 1.0f;
    d_nsrc[i] = ns; d_ndst[i] = nd;
    float gs = sqrtf(0.5f * __ldg(grav));                 // fold 0.5*g into masses
#pragma unroll
    for (int d0 = 0; d0 < D; d0++) {
        float m = M[(size_t)i * (D*D) + d0 * (D+1)];   // diagonal entry
        d_mdiag[i*D + d0] = m * gs;
        float qv = q[i*D + d0];
        d_qs[i*D + d0] = qv * ns;
        out[(size_t)i*16 + 8 + d0] = p[i*D + d0] / m;  // dHdP = M^{-1} p
    }
}

// generic 8-float edge gather/scatter (red.v4 atomics), 1 edge/thread
__device__ __forceinline__ void edge_agg(const int* __restrict__ gi, const int* __restrict__ si,
                                         const float* __restrict__ xin, float* xout, int e) {
    int i = blockIdx.x * blockDim.x + threadIdx.x;
    if (i >= e) return;
    int g = gi[i], s = si[i];
    const float4* ps = (const float4*)(xin + (size_t)g * D);
    float4 a = __ldg(ps), b = __ldg(ps + 1);
    float* po = xout + (size_t)s * D;
    red_add_v4(po, a);
    red_add_v4(po + 4, b);
}

__global__ void k_agg1(const int* __restrict__ src, const int* __restrict__ dst, int e)
{ edge_agg(src, dst, d_qs,  d_agg1, e); }
__global__ void k_agg2(const int* __restrict__ src, const int* __restrict__ dst, int e)
{ edge_agg(src, dst, d_ts,  d_agg2, e); }
__global__ void k_aggr2(const int* __restrict__ src, const int* __restrict__ dst, int e)
{ edge_agg(dst, src, d_gz1d, d_tmp2, e); }

// aggr1 folds the ndst scale into the gather: tmp1[src] += gH[dst] * ndst[dst]
__global__ void k_aggr1(const int* __restrict__ src, const int* __restrict__ dst, int e) {
    int i = blockIdx.x * blockDim.x + threadIdx.x;
    if (i >= e) return;
    int g = dst[i], s = src[i];
    float s0 = __ldg(&d_ndst[g]);
    const float4* ps = (const float4*)(d_gH + (size_t)g * D);
    float4 a = __ldg(ps), b = __ldg(ps + 1);
    a.x *= s0; a.y *= s0; a.z *= s0; a.w *= s0;
    b.x *= s0; b.y *= s0; b.z *= s0; b.w *= s0;
    float* po = d_tmp1 + (size_t)s * D;
    red_add_v4(po, a); red_add_v4(po + 4, b);
}

// ---------------- MLP forward: 2 threads per node (j split in halves) --------
// Even thread: j in [0,128); odd thread: j in [128,256). Partial t[8] combined
// via shfl_xor(1). Scalar FMA inner loop (R6-proven form).
__global__ __launch_bounds__(256) void k_mlp_fwd(const float* __restrict__ W1,
                                                 const float* __restrict__ b1,
                                                 const float* __restrict__ W2, int n) {
    __shared__ float4 sW1[H][2];   // W1 transposed: sW1[j] = W1[:, j]
    __shared__ float4 sW2[H][2];   // W2[j, :]
    __shared__ float  sb1[H];
    int tid = threadIdx.x;
    if (tid < H) {
        int j = tid;
        float4 wa, wb;
        wa.x = W1[0*H + j]; wa.y = W1[1*H + j]; wa.z = W1[2*H + j]; wa.w = W1[3*H + j];
        wb.x = W1[4*H + j]; wb.y = W1[5*H + j]; wb.z = W1[6*H + j]; wb.w = W1[7*H + j];
        sW1[j][0] = wa; sW1[j][1] = wb;
        sW2[j][0] = ((const float4*)W2)[j*2];
        sW2[j][1] = ((const float4*)W2)[j*2 + 1];
        sb1[j] = b1[j];
    }
    __syncthreads();
    int t = blockIdx.x * blockDim.x + tid;
    int i = t >> 1;            // node
    int half = t & 1;          // j-half
    if (i >= n) return;
    float nd = d_ndst[i];
    float4* pz = (float4*)(d_agg1 + (size_t)i * D);
    float4 z0 = pz[0], z1 = pz[1];
    if (half == 0) {                                     // restore invariant once
        pz[0] = make_float4(0.f,0.f,0.f,0.f);
        pz[1] = make_float4(0.f,0.f,0.f,0.f);
    }
    z0.x *= nd; z0.y *= nd; z0.z *= nd; z0.w *= nd;
    z1.x *= nd; z1.y *= nd; z1.z *= nd; z1.w *= nd;
    float4 t0 = make_float4(0.f,0.f,0.f,0.f), t1 = make_float4(0.f,0.f,0.f,0.f);
    unsigned mword = 0;
    int jbeg = half * (H/2), jend = jbeg + (H/2);
#pragma unroll 8
    for (int j = jbeg; j < jend; j++) {
        float4 wa = sW1[j][0], wb = sW1[j][1];
        float y = sb1[j];
        y += z0.x*wa.x + z0.y*wa.y + z0.z*wa.z + z0.w*wa.w;
        y += z1.x*wb.x + z1.y*wb.y + z1.z*wb.z + z1.w*wb.w;
        unsigned on = (y > 0.f) ? 1u : 0u;
        mword |= on << (j & 31);
        if ((j & 31) == 31) { d_mask[(size_t)i*MASKW + (j >> 5)] = mword; mword = 0; }
        float r = on ? y : 0.f;
        float4 va = sW2[j][0], vb = sW2[j][1];
        t0.x += r*va.x; t0.y += r*va.y; t0.z += r*va.z; t0.w += r*va.w;
        t1.x += r*vb.x; t1.y += r*vb.y; t1.z += r*vb.z; t1.w += r*vb.w;
    }
    // combine the two halves (pair = lanes differing in bit 0)
    t0.x += __shfl_xor_sync(0xffffffffu, t0.x, 1);
    t0.y += __shfl_xor_sync(0xffffffffu, t0.y, 1);
    t0.z += __shfl_xor_sync(0xffffffffu, t0.z, 1);
    t0.w += __shfl_xor_sync(0xffffffffu, t0.w, 1);
    t1.x += __shfl_xor_sync(0xffffffffu, t1.x, 1);
    t1.y += __shfl_xor_sync(0xffffffffu, t1.y, 1);
    t1.z += __shfl_xor_sync(0xffffffffu, t1.z, 1);
    t1.w += __shfl_xor_sync(0xffffffffu, t1.w, 1);
    if (half == 0) {
        float ns = d_nsrc[i];
        t0.x *= ns; t0.y *= ns; t0.z *= ns; t0.w *= ns;
        t1.x *= ns; t1.y *= ns; t1.z *= ns; t1.w *= ns;
        float4* po = (float4*)(d_ts + (size_t)i * D);
        po[0] = t0; po[1] = t1;
    }
}

// h = agg2*nd + b2 + q; zero agg2
__global__ void k_h(const float* __restrict__ q, const float* __restrict__ b2, int n) {
    int i = blockIdx.x * blockDim.x + threadIdx.x;
    if (i >= n) return;
    float nd = d_ndst[i];
#pragma unroll
    for (int d0 = 0; d0 < D; d0++) {
        d_h[i*D + d0] = d_agg2[i*D + d0] * nd + __ldg(&b2[d0]) + q[i*D + d0];
        d_agg2[i*D + d0] = 0.f;                           // restore invariant
    }
}

// pairwise force: gH[src] += a, gH[dst] -= a ; a = -c*(hs-hd)/r^3
// (0.5*g already folded into d_mdiag at prep)
__global__ void k_force(const int* __restrict__ src, const int* __restrict__ dst, int e) {
    int i = blockIdx.x * blockDim.x + threadIdx.x;
    if (i >= e) return;
    int s = src[i], t = dst[i];
    const float4* phs = (const float4*)(d_h + (size_t)s * D);
    const float4* phd = (const float4*)(d_h + (size_t)t * D);
    const float4* pms = (const float4*)(d_mdiag + (size_t)s * D);
    const float4* pmd = (const float4*)(d_mdiag + (size_t)t * D);
    float4 hs0 = __ldg(phs), hs1 = __ldg(phs+1);
    float4 hd0 = __ldg(phd), hd1 = __ldg(phd+1);
    float4 ms0 = __ldg(pms), ms1 = __ldg(pms+1);
    float4 md0 = __ldg(pmd), md1 = __ldg(pmd+1);
    float c = ms0.x*md0.x + ms0.y*md0.y + ms0.z*md0.z + ms0.w*md0.w
            + ms1.x*md1.x + ms1.y*md1.y + ms1.z*md1.z + ms1.w*md1.w;
    float4 f0, f1;
    f0.x = hs0.x - hd0.x; f0.y = hs0.y - hd0.y; f0.z = hs0.z - hd0.z; f0.w = hs0.w - hd0.w;
    f1.x = hs1.x - hd1.x; f1.y = hs1.y - hd1.y; f1.z = hs1.z - hd1.z; f1.w = hs1.w - hd1.w;
    float r2 = f0.x*f0.x + f0.y*f0.y + f0.z*f0.z + f0.w*f0.w
             + f1.x*f1.x + f1.y*f1.y + f1.z*f1.z + f1.w*f1.w;
    float inv = rsqrtf(r2);
    float coef = -c * inv * inv * inv;
    float4 a0, a1, n0, n1;
    a0.x = coef*f0.x; a0.y = coef*f0.y; a0.z = coef*f0.z; a0.w = coef*f0.w;
    a1.x = coef*f1.x; a1.y = coef*f1.y; a1.z = coef*f1.z; a1.w = coef*f1.w;
    n0.x = -a0.x; n0.y = -a0.y; n0.z = -a0.z; n0.w = -a0.w;
    n1.x = -a1.x; n1.y = -a1.y; n1.z = -a1.z; n1.w = -a1.w;
    float* ps = d_gH + (size_t)s * D;
    float* pt = d_gH + (size_t)t * D;
    red_add_v4(ps, a0); red_add_v4(ps + 4, a1);
    red_add_v4(pt, n0); red_add_v4(pt + 4, n1);
}

// ---------------- MLP backward: 2 threads per node (j split) -----------------
// gt = tmp1*ns; gh1 = gt W2^T; *mask; gz1 = gh1 W1^T; gz1d = gz1*nd; zero tmp1.
__global__ __launch_bounds__(256) void k_mlp_bwd(const float* __restrict__ W1,
                                                 const float* __restrict__ W2, int n) {
    __shared__ float4 sW1[H][2];
    __shared__ float4 sW2[H][2];
    int tid = threadIdx.x;
    if (tid < H) {
        int j = tid;
        float4 wa, wb;
        wa.x = W1[0*H + j]; wa.y = W1[1*H + j]; wa.z = W1[2*H + j]; wa.w = W1[3*H + j];
        wb.x = W1[4*H + j]; wb.y = W1[5*H + j]; wb.z = W1[6*H + j]; wb.w = W1[7*H + j];
        sW1[j][0] = wa; sW1[j][1] = wb;
        sW2[j][0] = ((const float4*)W2)[j*2];
        sW2[j][1] = ((const float4*)W2)[j*2 + 1];
    }
    __syncthreads();
    int t = blockIdx.x * blockDim.x + tid;
    int i = t >> 1;
    int half = t & 1;
    if (i >= n) return;
    float ns = d_nsrc[i];
    float4* pg = (float4*)(d_tmp1 + (size_t)i * D);
    float4 g0 = pg[0], g1 = pg[1];
    if (half == 0) {                                     // restore invariant once
        pg[0] = make_float4(0.f,0.f,0.f,0.f);
        pg[1] = make_float4(0.f,0.f,0.f,0.f);
    }
    g0.x *= ns; g0.y *= ns; g0.z *= ns; g0.w *= ns;
    g1.x *= ns; g1.y *= ns; g1.z *= ns; g1.w *= ns;
    float4 z0 = make_float4(0.f,0.f,0.f,0.f), z1 = make_float4(0.f,0.f,0.f,0.f);
    int jbeg = half * (H/2), jend = jbeg + (H/2);
    unsigned mword = 0;
#pragma unroll 8
    for (int j = jbeg; j < jend; j++) {
        if ((j & 31) == 0) mword = d_mask[(size_t)i*MASKW + (j >> 5)];
        float4 va = sW2[j][0], vb = sW2[j][1];
        float gh = g0.x*va.x + g0.y*va.y + g0.z*va.z + g0.w*va.w
                 + g1.x*vb.x + g1.y*vb.y + g1.z*vb.z + g1.w*vb.w;
        gh *= (float)((mword >> (j & 31)) & 1u);   // relu'(y1)
        float4 wa = sW1[j][0], wb = sW1[j][1];
        z0.x += gh*wa.x; z0.y += gh*wa.y; z0.z += gh*wa.z; z0.w += gh*wa.w;
        z1.x += gh*wb.x; z1.y += gh*wb.y; z1.z += gh*wb.z; z1.w += gh*wb.w;
    }
    z0.x += __shfl_xor_sync(0xffffffffu, z0.x, 1);
    z0.y += __shfl_xor_sync(0xffffffffu, z0.y, 1);
    z0.z += __shfl_xor_sync(0xffffffffu, z0.z, 1);
    z0.w += __shfl_xor_sync(0xffffffffu, z0.w, 1);
    z1.x += __shfl_xor_sync(0xffffffffu, z1.x, 1);
    z1.y += __shfl_xor_sync(0xffffffffu, z1.y, 1);
    z1.z += __shfl_xor_sync(0xffffffffu, z1.z, 1);
    z1.w += __shfl_xor_sync(0xffffffffu, z1.w, 1);
    if (half == 0) {
        float nd = d_ndst[i];
        z0.x *= nd; z0.y *= nd; z0.z *= nd; z0.w *= nd;
        z1.x *= nd; z1.y *= nd; z1.z *= nd; z1.w *= nd;
        float4* po = (float4*)(d_gz1d + (size_t)i * D);
        po[0] = z0; po[1] = z1;
    }
}

// out[:, 0:8] = gH + nsrc * tmp2; zero gH, tmp2
__global__ void k_final(float* __restrict__ out, int n) {
    int i = blockIdx.x * blockDim.x + threadIdx.x;
    if (i >= n) return;
    float ns = d_nsrc[i];
#pragma unroll
    for (int d0 = 0; d0 < D; d0++) {
        out[(size_t)i*16 + d0] = d_gH[i*D + d0] + ns * d_tmp2[i*D + d0];
        d_gH[i*D + d0] = 0.f;                             // restore invariant
        d_tmp2[i*D + d0] = 0.f;
    }
}

// ---------------- launch ----------------------------------------------------
extern "C" void kernel_launch(void* const* d_in, const int* in_sizes, int n_in,
                              void* d_out, int out_size) {
    const float* q    = (const float*)d_in[0];
    const float* p    = (const float*)d_in[1];
    const float* M    = (const float*)d_in[2];
    const int*   src  = (const int*)  d_in[3];
    const int*   dst  = (const int*)  d_in[4];
    const float* W1   = (const float*)d_in[5];
    const float* b1   = (const float*)d_in[6];
    const float* W2   = (const float*)d_in[7];
    const float* b2   = (const float*)d_in[8];
    const float* grav = (const float*)d_in[9];
    float* out = (float*)d_out;

    int n = in_sizes[0] / D;
    int e = in_sizes[3];
    int nb_n  = (n + 255) / 256;
    int nb_m  = (2*n + 255) / 256;   // MLP: 2 threads per node
    int nb_e  = (e + 255) / 256;

    k_deg    <<<nb_e,  256>>>(src, dst, e);
    k_prep   <<<nb_n,  256>>>(q, p, M, grav, out, n);
    k_agg1   <<<nb_e,  256>>>(src, dst, e);
    k_mlp_fwd<<<nb_m,  256>>>(W1, b1, W2, n);
    k_agg2   <<<nb_e,  256>>>(src, dst, e);
    k_h      <<<nb_n,  256>>>(q, b2, n);
    k_force  <<<nb_e,  256>>>(src, dst, e);
    k_aggr1  <<<nb_e,  256>>>(src, dst, e);
    k_mlp_bwd<<<nb_m,  256>>>(W1, W2, n);
    k_aggr2  <<<nb_e,  256>>>(src, dst, e);
    k_final  <<<nb_n,  256>>>(out, n);
}

// round 16
// speedup vs baseline: 1.8371x; 1.8371x over previous
#include <cuda_runtime.h>

#define D 8
#define H 256
#define MAXN 100352
#define MASKW (H/32)
#define NPT 2   // nodes per thread in MLP kernels (grid stays >= 148 blocks)

// ---------------- scratch (device globals; zero-initialized at module load).
// Invariant: accumulator arrays are zero on entry to kernel_launch and are
// re-zeroed by the kernel that consumes them (graph-replay safe).
__device__ float d_mdiag[MAXN*D];  // mass diag pre-scaled by sqrt(0.5*g)
__device__ float d_qs[MAXN*D];     // q * norm_src
__device__ float d_nsrc[MAXN];
__device__ float d_ndst[MAXN];
__device__ int   d_degout[MAXN];   // accumulator (zeroed by k_prep)
__device__ int   d_degin[MAXN];    // accumulator (zeroed by k_prep)
__device__ float d_agg1[MAXN*D];   // accumulator (zeroed by k_mlp_fwd)
__device__ float d_ts[MAXN*D];
__device__ float d_agg2[MAXN*D];   // accumulator (zeroed by k_h)
__device__ float d_h[MAXN*D];
__device__ float d_gH[MAXN*D];     // accumulator (zeroed by k_final)
__device__ float d_gz1d[MAXN*D];
__device__ float d_tmp1[MAXN*D];   // accumulator (zeroed by k_mlp_bwd)
__device__ float d_tmp2[MAXN*D];   // accumulator (zeroed by k_final)
__device__ unsigned d_mask[MAXN*MASKW];

// ---------------- helpers ---------------------------------------------------
__device__ __forceinline__ void red_add_v4(float* p, float4 v) {
    asm volatile("red.global.add.v4.f32 [%0], {%1,%2,%3,%4};"
                 :: "l"(p), "f"(v.x), "f"(v.y), "f"(v.z), "f"(v.w) : "memory");
}

// ---------------- kernels ---------------------------------------------------
__global__ void k_deg(const int* __restrict__ src, const int* __restrict__ dst, int e) {
    int i = blockIdx.x * blockDim.x + threadIdx.x;
    if (i >= e) return;
    atomicAdd(&d_degout[src[i]], 1);
    atomicAdd(&d_degin[dst[i]], 1);
}

// norms, mass diag (pre-scaled by sqrt(0.5*g)), qs pre-scale, dHdP; zero deg
__global__ void k_prep(const float* __restrict__ q, const float* __restrict__ p,
                       const float* __restrict__ M, const float* __restrict__ grav,
                       float* __restrict__ out, int n) {
    int i = blockIdx.x * blockDim.x + threadIdx.x;
    if (i >= n) return;
    int dout = d_degout[i], din = d_degin[i];
    d_degout[i] = 0; d_degin[i] = 0;                      // restore invariant
    float ns = (dout > 0) ? rsqrtf((float)dout) : 1.0f;
    float nd = (din  > 0) ? rsqrtf((float)din)  : 1.0f;
    d_nsrc[i] = ns; d_ndst[i] = nd;
    float gs = sqrtf(0.5f * __ldg(grav));                 // fold 0.5*g into masses
#pragma unroll
    for (int d0 = 0; d0 < D; d0++) {
        float m = M[(size_t)i * (D*D) + d0 * (D+1)];   // diagonal entry
        d_mdiag[i*D + d0] = m * gs;
        float qv = q[i*D + d0];
        d_qs[i*D + d0] = qv * ns;
        out[(size_t)i*16 + 8 + d0] = p[i*D + d0] / m;  // dHdP = M^{-1} p
    }
}

// generic 8-float edge gather/scatter (red.v4 atomics), 1 edge/thread
__device__ __forceinline__ void edge_agg(const int* __restrict__ gi, const int* __restrict__ si,
                                         const float* __restrict__ xin, float* xout, int e) {
    int i = blockIdx.x * blockDim.x + threadIdx.x;
    if (i >= e) return;
    int g = gi[i], s = si[i];
    const float4* ps = (const float4*)(xin + (size_t)g * D);
    float4 a = __ldg(ps), b = __ldg(ps + 1);
    float* po = xout + (size_t)s * D;
    red_add_v4(po, a);
    red_add_v4(po + 4, b);
}

__global__ void k_agg1(const int* __restrict__ src, const int* __restrict__ dst, int e)
{ edge_agg(src, dst, d_qs,  d_agg1, e); }
__global__ void k_agg2(const int* __restrict__ src, const int* __restrict__ dst, int e)
{ edge_agg(src, dst, d_ts,  d_agg2, e); }
__global__ void k_aggr2(const int* __restrict__ src, const int* __restrict__ dst, int e)
{ edge_agg(dst, src, d_gz1d, d_tmp2, e); }

// aggr1 folds the ndst scale into the gather: tmp1[src] += gH[dst] * ndst[dst]
__global__ void k_aggr1(const int* __restrict__ src, const int* __restrict__ dst, int e) {
    int i = blockIdx.x * blockDim.x + threadIdx.x;
    if (i >= e) return;
    int g = dst[i], s = src[i];
    float s0 = __ldg(&d_ndst[g]);
    const float4* ps = (const float4*)(d_gH + (size_t)g * D);
    float4 a = __ldg(ps), b = __ldg(ps + 1);
    a.x *= s0; a.y *= s0; a.z *= s0; a.w *= s0;
    b.x *= s0; b.y *= s0; b.z *= s0; b.w *= s0;
    float* po = d_tmp1 + (size_t)s * D;
    red_add_v4(po, a); red_add_v4(po + 4, b);
}

// ---------------- MLP forward, NPT=2 nodes/thread, scalar FMA ----------------
// z1 = agg1*nd; y1 = z1 W1 + b1; mask; t = relu(y1) W2; ts = t*ns; zero agg1.
// Warp-uniform j (broadcast LDS); weight LDS amortized over 2 nodes.
__global__ __launch_bounds__(256) void k_mlp_fwd(const float* __restrict__ W1,
                                                 const float* __restrict__ b1,
                                                 const float* __restrict__ W2, int n) {
    __shared__ float4 sW1[H][2];   // W1 transposed: sW1[j] = W1[:, j]
    __shared__ float4 sW2[H][2];   // W2[j, :]
    __shared__ float  sb1[H];
    int tid = threadIdx.x;
    {
        int j = tid;
        float4 wa, wb;
        wa.x = W1[0*H + j]; wa.y = W1[1*H + j]; wa.z = W1[2*H + j]; wa.w = W1[3*H + j];
        wb.x = W1[4*H + j]; wb.y = W1[5*H + j]; wb.z = W1[6*H + j]; wb.w = W1[7*H + j];
        sW1[j][0] = wa; sW1[j][1] = wb;
        sW2[j][0] = ((const float4*)W2)[j*2];
        sW2[j][1] = ((const float4*)W2)[j*2 + 1];
        sb1[j] = b1[j];
    }
    __syncthreads();
    int i0 = (blockIdx.x * blockDim.x + tid) * NPT;
    if (i0 >= n) return;
    float z[NPT][D], t[NPT][D];
#pragma unroll
    for (int k = 0; k < NPT; k++) {
        int i = i0 + k;
        float nd = d_ndst[i];
        float4* pz = (float4*)(d_agg1 + (size_t)i * D);
        float4 z0 = pz[0], z1 = pz[1];
        pz[0] = make_float4(0.f,0.f,0.f,0.f);           // restore invariant
        pz[1] = make_float4(0.f,0.f,0.f,0.f);
        z[k][0] = z0.x*nd; z[k][1] = z0.y*nd; z[k][2] = z0.z*nd; z[k][3] = z0.w*nd;
        z[k][4] = z1.x*nd; z[k][5] = z1.y*nd; z[k][6] = z1.z*nd; z[k][7] = z1.w*nd;
#pragma unroll
        for (int d0 = 0; d0 < D; d0++) t[k][d0] = 0.f;
    }
    unsigned mw[NPT] = {0, 0};
#pragma unroll 4
    for (int j = 0; j < H; j++) {
        float4 wa = sW1[j][0], wb = sW1[j][1];
        float  bb = sb1[j];
        float4 va = sW2[j][0], vb = sW2[j][1];
#pragma unroll
        for (int k = 0; k < NPT; k++) {
            float y = bb;
            y += z[k][0]*wa.x + z[k][1]*wa.y + z[k][2]*wa.z + z[k][3]*wa.w;
            y += z[k][4]*wb.x + z[k][5]*wb.y + z[k][6]*wb.z + z[k][7]*wb.w;
            unsigned on = (y > 0.f) ? 1u : 0u;
            mw[k] |= on << (j & 31);
            float r = on ? y : 0.f;
            t[k][0] += r*va.x; t[k][1] += r*va.y; t[k][2] += r*va.z; t[k][3] += r*va.w;
            t[k][4] += r*vb.x; t[k][5] += r*vb.y; t[k][6] += r*vb.z; t[k][7] += r*vb.w;
        }
        if ((j & 31) == 31) {
#pragma unroll
            for (int k = 0; k < NPT; k++) {
                d_mask[(size_t)(i0 + k)*MASKW + (j >> 5)] = mw[k];
                mw[k] = 0;
            }
        }
    }
#pragma unroll
    for (int k = 0; k < NPT; k++) {
        int i = i0 + k;
        float ns = d_nsrc[i];
        float4* po = (float4*)(d_ts + (size_t)i * D);
        po[0] = make_float4(t[k][0]*ns, t[k][1]*ns, t[k][2]*ns, t[k][3]*ns);
        po[1] = make_float4(t[k][4]*ns, t[k][5]*ns, t[k][6]*ns, t[k][7]*ns);
    }
}

// h = agg2*nd + b2 + q; zero agg2
__global__ void k_h(const float* __restrict__ q, const float* __restrict__ b2, int n) {
    int i = blockIdx.x * blockDim.x + threadIdx.x;
    if (i >= n) return;
    float nd = d_ndst[i];
#pragma unroll
    for (int d0 = 0; d0 < D; d0++) {
        d_h[i*D + d0] = d_agg2[i*D + d0] * nd + __ldg(&b2[d0]) + q[i*D + d0];
        d_agg2[i*D + d0] = 0.f;                           // restore invariant
    }
}

// pairwise force: gH[src] += a, gH[dst] -= a ; a = -c*(hs-hd)/r^3
// (0.5*g already folded into d_mdiag at prep)
__global__ void k_force(const int* __restrict__ src, const int* __restrict__ dst, int e) {
    int i = blockIdx.x * blockDim.x + threadIdx.x;
    if (i >= e) return;
    int s = src[i], t = dst[i];
    const float4* phs = (const float4*)(d_h + (size_t)s * D);
    const float4* phd = (const float4*)(d_h + (size_t)t * D);
    const float4* pms = (const float4*)(d_mdiag + (size_t)s * D);
    const float4* pmd = (const float4*)(d_mdiag + (size_t)t * D);
    float4 hs0 = __ldg(phs), hs1 = __ldg(phs+1);
    float4 hd0 = __ldg(phd), hd1 = __ldg(phd+1);
    float4 ms0 = __ldg(pms), ms1 = __ldg(pms+1);
    float4 md0 = __ldg(pmd), md1 = __ldg(pmd+1);
    float c = ms0.x*md0.x + ms0.y*md0.y + ms0.z*md0.z + ms0.w*md0.w
            + ms1.x*md1.x + ms1.y*md1.y + ms1.z*md1.z + ms1.w*md1.w;
    float4 f0, f1;
    f0.x = hs0.x - hd0.x; f0.y = hs0.y - hd0.y; f0.z = hs0.z - hd0.z; f0.w = hs0.w - hd0.w;
    f1.x = hs1.x - hd1.x; f1.y = hs1.y - hd1.y; f1.z = hs1.z - hd1.z; f1.w = hs1.w - hd1.w;
    float r2 = f0.x*f0.x + f0.y*f0.y + f0.z*f0.z + f0.w*f0.w
             + f1.x*f1.x + f1.y*f1.y + f1.z*f1.z + f1.w*f1.w;
    float inv = rsqrtf(r2);
    float coef = -c * inv * inv * inv;
    float4 a0, a1, n0, n1;
    a0.x = coef*f0.x; a0.y = coef*f0.y; a0.z = coef*f0.z; a0.w = coef*f0.w;
    a1.x = coef*f1.x; a1.y = coef*f1.y; a1.z = coef*f1.z; a1.w = coef*f1.w;
    n0.x = -a0.x; n0.y = -a0.y; n0.z = -a0.z; n0.w = -a0.w;
    n1.x = -a1.x; n1.y = -a1.y; n1.z = -a1.z; n1.w = -a1.w;
    float* ps = d_gH + (size_t)s * D;
    float* pt = d_gH + (size_t)t * D;
    red_add_v4(ps, a0); red_add_v4(ps + 4, a1);
    red_add_v4(pt, n0); red_add_v4(pt + 4, n1);
}

// ---------------- MLP backward, NPT=2 nodes/thread, scalar FMA ---------------
// gt = tmp1*ns; gh1 = gt W2^T; *mask; gz1 = gh1 W1^T; gz1d = gz1*nd; zero tmp1.
__global__ __launch_bounds__(256) void k_mlp_bwd(const float* __restrict__ W1,
                                                 const float* __restrict__ W2, int n) {
    __shared__ float4 sW1[H][2];
    __shared__ float4 sW2[H][2];
    int tid = threadIdx.x;
    {
        int j = tid;
        float4 wa, wb;
        wa.x = W1[0*H + j]; wa.y = W1[1*H + j]; wa.z = W1[2*H + j]; wa.w = W1[3*H + j];
        wb.x = W1[4*H + j]; wb.y = W1[5*H + j]; wb.z = W1[6*H + j]; wb.w = W1[7*H + j];
        sW1[j][0] = wa; sW1[j][1] = wb;
        sW2[j][0] = ((const float4*)W2)[j*2];
        sW2[j][1] = ((const float4*)W2)[j*2 + 1];
    }
    __syncthreads();
    int i0 = (blockIdx.x * blockDim.x + tid) * NPT;
    if (i0 >= n) return;
    float g[NPT][D], zc[NPT][D];
#pragma unroll
    for (int k = 0; k < NPT; k++) {
        int i = i0 + k;
        float ns = d_nsrc[i];
        float4* pg = (float4*)(d_tmp1 + (size_t)i * D);
        float4 g0 = pg[0], g1 = pg[1];
        pg[0] = make_float4(0.f,0.f,0.f,0.f);           // restore invariant
        pg[1] = make_float4(0.f,0.f,0.f,0.f);
        g[k][0] = g0.x*ns; g[k][1] = g0.y*ns; g[k][2] = g0.z*ns; g[k][3] = g0.w*ns;
        g[k][4] = g1.x*ns; g[k][5] = g1.y*ns; g[k][6] = g1.z*ns; g[k][7] = g1.w*ns;
#pragma unroll
        for (int d0 = 0; d0 < D; d0++) zc[k][d0] = 0.f;
    }
    unsigned mw[NPT];
#pragma unroll 4
    for (int j = 0; j < H; j++) {
        if ((j & 31) == 0) {
#pragma unroll
            for (int k = 0; k < NPT; k++)
                mw[k] = d_mask[(size_t)(i0 + k)*MASKW + (j >> 5)];
        }
        float4 va = sW2[j][0], vb = sW2[j][1];
        float4 wa = sW1[j][0], wb = sW1[j][1];
#pragma unroll
        for (int k = 0; k < NPT; k++) {
            float gh = g[k][0]*va.x + g[k][1]*va.y + g[k][2]*va.z + g[k][3]*va.w
                     + g[k][4]*vb.x + g[k][5]*vb.y + g[k][6]*vb.z + g[k][7]*vb.w;
            gh *= (float)((mw[k] >> (j & 31)) & 1u);     // relu'(y1)
            zc[k][0] += gh*wa.x; zc[k][1] += gh*wa.y; zc[k][2] += gh*wa.z; zc[k][3] += gh*wa.w;
            zc[k][4] += gh*wb.x; zc[k][5] += gh*wb.y; zc[k][6] += gh*wb.z; zc[k][7] += gh*wb.w;
        }
    }
#pragma unroll
    for (int k = 0; k < NPT; k++) {
        int i = i0 + k;
        float nd = d_ndst[i];
        float4* po = (float4*)(d_gz1d + (size_t)i * D);
        po[0] = make_float4(zc[k][0]*nd, zc[k][1]*nd, zc[k][2]*nd, zc[k][3]*nd);
        po[1] = make_float4(zc[k][4]*nd, zc[k][5]*nd, zc[k][6]*nd, zc[k][7]*nd);
    }
}

// out[:, 0:8] = gH + nsrc * tmp2; zero gH, tmp2
__global__ void k_final(float* __restrict__ out, int n) {
    int i = blockIdx.x * blockDim.x + threadIdx.x;
    if (i >= n) return;
    float ns = d_nsrc[i];
#pragma unroll
    for (int d0 = 0; d0 < D; d0++) {
        out[(size_t)i*16 + d0] = d_gH[i*D + d0] + ns * d_tmp2[i*D + d0];
        d_gH[i*D + d0] = 0.f;                             // restore invariant
        d_tmp2[i*D + d0] = 0.f;
    }
}

// ---------------- launch ----------------------------------------------------
extern "C" void kernel_launch(void* const* d_in, const int* in_sizes, int n_in,
                              void* d_out, int out_size) {
    const float* q    = (const float*)d_in[0];
    const float* p    = (const float*)d_in[1];
    const float* M    = (const float*)d_in[2];
    const int*   src  = (const int*)  d_in[3];
    const int*   dst  = (const int*)  d_in[4];
    const float* W1   = (const float*)d_in[5];
    const float* b1   = (const float*)d_in[6];
    const float* W2   = (const float*)d_in[7];
    const float* b2   = (const float*)d_in[8];
    const float* grav = (const float*)d_in[9];
    float* out = (float*)d_out;

    int n = in_sizes[0] / D;
    int e = in_sizes[3];
    int nb_n  = (n + 255) / 256;
    int nb_m  = ((n + NPT - 1) / NPT + 255) / 256;   // MLP: 2 nodes/thread
    int nb_e  = (e + 255) / 256;

    k_deg    <<<nb_e,  256>>>(src, dst, e);
    k_prep   <<<nb_n,  256>>>(q, p, M, grav, out, n);
    k_agg1   <<<nb_e,  256>>>(src, dst, e);
    k_mlp_fwd<<<nb_m,  256>>>(W1, b1, W2, n);
    k_agg2   <<<nb_e,  256>>>(src, dst, e);
    k_h      <<<nb_n,  256>>>(q, b2, n);
    k_force  <<<nb_e,  256>>>(src, dst, e);
    k_aggr1  <<<nb_e,  256>>>(src, dst, e);
    k_mlp_bwd<<<nb_m,  256>>>(W1, W2, n);
    k_aggr2  <<<nb_e,  256>>>(src, dst, e);
    k_final  <<<nb_n,  256>>>(out, n);
}